// round 1
// baseline (speedup 1.0000x reference)
#include <cuda_runtime.h>
#include <math.h>

// Problem constants (from reference: BW=8, WINDOW=2 -> B=4; C=128, N=512, H=W=256)
#define B_   4
#define C_   128
#define N_   512
#define H_   256
#define W_   256
#define HW_  65536
#define MT_  512           // number of 128-wide m tiles per row (HW/128)

// Output layout: pseudo_coords (4,512,2) | match_weights (4,1,512) | soft_match (4,512,65536)
#define OUT_MW   (B_ * N_ * 2)            // 4096
#define OUT_SOFT (B_ * N_ * 2 + B_ * N_)  // 6144

// ---- device scratch (static allocation: allowed) ----
__device__ float g_src[B_][C_][N_];     // L2-normalized keypoint descriptors, k-major [b][c][n]
__device__ float g_invn[B_][HW_];       // 1/||dense desc column||
__device__ float g_pe[B_][N_][MT_];     // per-(row, mtile) partial sum of e
__device__ float g_pu[B_][N_][MT_];     // per-(row, mtile) partial sum of e*u
__device__ float g_red[B_][N_][3];      // inv_denom, u, v

// ---------------------------------------------------------------------------
// Normalize keypoint descriptors of the kp_inds batches into g_src[b][c][n]
// ---------------------------------------------------------------------------
__global__ void k_norm_kp(const float* __restrict__ kp_desc) {
    int t = blockIdx.x * blockDim.x + threadIdx.x;     // 0 .. B_*N_-1
    if (t >= B_ * N_) return;
    int b = t / N_, n = t - b * N_;
    const float* src = kp_desc + (size_t)(2 * b) * C_ * N_ + n;
    float s = 0.f;
#pragma unroll 8
    for (int c = 0; c < C_; ++c) { float v = src[(size_t)c * N_]; s += v * v; }
    float inv = 1.f / fmaxf(sqrtf(s), 1e-12f);
#pragma unroll 8
    for (int c = 0; c < C_; ++c) g_src[b][c][n] = src[(size_t)c * N_] * inv;
}

// ---------------------------------------------------------------------------
// Inverse L2 norm per dense column (b, m) over C
// ---------------------------------------------------------------------------
__global__ void k_invn(const float* __restrict__ dense) {
    int t = blockIdx.x * blockDim.x + threadIdx.x;     // 0 .. B_*HW_-1
    int b = t >> 16, m = t & (HW_ - 1);
    const float* p = dense + (size_t)(2 * b + 1) * C_ * HW_ + m;
    float s = 0.f;
#pragma unroll 8
    for (int c = 0; c < C_; ++c) { float v = p[(size_t)c * HW_]; s += v * v; }
    g_invn[b][m] = 1.f / fmaxf(sqrtf(s), 1e-12f);
}

// ---------------------------------------------------------------------------
// GEMM (128x128 tile, K=128) + fused exp epilogue.
// Writes e = exp(100 * cos_sim) into the soft_match output region and
// deterministic per-(row, mtile) partials (sum e, sum e*u).
// grid: (4 ntiles, 512 mtiles, 4 b) -- x fastest so blocks sharing an m-tile
// run adjacently (L2 reuse of the 64KB dense tile).
// ---------------------------------------------------------------------------
__global__ void __launch_bounds__(256, 2) k_gemm(const float* __restrict__ dense,
                                                 float* __restrict__ out) {
    const int nt = blockIdx.x, mt = blockIdx.y, b = blockIdx.z;
    const int n0 = nt * 128, m0 = mt * 128;

    __shared__ float As[16][128];
    __shared__ float Bs[16][128];

    const float* Ag = &g_src[b][0][0];                              // [C_][N_]
    const float* Bg = dense + (size_t)(2 * b + 1) * C_ * HW_;       // [C_][HW_]

    const int t  = threadIdx.x;
    const int lr = t >> 4;            // 0..15 (k-row within chunk)
    const int lc = (t & 15) * 8;      // 0..120 (col, 8-wide)
    const int tx = t & 15, ty = t >> 4;

    float acc[8][8];
#pragma unroll
    for (int i = 0; i < 8; ++i)
#pragma unroll
        for (int j = 0; j < 8; ++j) acc[i][j] = 0.f;

#pragma unroll 1
    for (int kc = 0; kc < C_; kc += 16) {
        const float4* ap = (const float4*)(Ag + (size_t)(kc + lr) * N_  + n0 + lc);
        const float4* bp = (const float4*)(Bg + (size_t)(kc + lr) * HW_ + m0 + lc);
        float4 a0 = ap[0], a1 = ap[1];
        float4 b0 = bp[0], b1 = bp[1];
        *(float4*)&As[lr][lc]     = a0;
        *(float4*)&As[lr][lc + 4] = a1;
        *(float4*)&Bs[lr][lc]     = b0;
        *(float4*)&Bs[lr][lc + 4] = b1;
        __syncthreads();
#pragma unroll
        for (int kk = 0; kk < 16; ++kk) {
            float ar[8], br[8];
            *(float4*)&ar[0] = *(float4*)&As[kk][ty * 8];
            *(float4*)&ar[4] = *(float4*)&As[kk][ty * 8 + 4];
            *(float4*)&br[0] = *(float4*)&Bs[kk][tx * 8];
            *(float4*)&br[4] = *(float4*)&Bs[kk][tx * 8 + 4];
#pragma unroll
            for (int i = 0; i < 8; ++i)
#pragma unroll
                for (int j = 0; j < 8; ++j) acc[i][j] = fmaf(ar[i], br[j], acc[i][j]);
        }
        __syncthreads();
    }

    // epilogue: scale by inv dense norm, exp(100*x), store e, accumulate partials
    float invn[8];
    *(float4*)&invn[0] = *(const float4*)&g_invn[b][m0 + tx * 8];
    *(float4*)&invn[4] = *(const float4*)&g_invn[b][m0 + tx * 8 + 4];
    const float u_base = (float)((m0 & 255) + tx * 8);   // tile never wraps W

    float* soft = out + OUT_SOFT;
#pragma unroll
    for (int i = 0; i < 8; ++i) {
        const int n = n0 + ty * 8 + i;
        float e[8];
        float se = 0.f, su = 0.f;
#pragma unroll
        for (int j = 0; j < 8; ++j) {
            float lg = 100.f * acc[i][j] * invn[j];
            float ev = __expf(lg);
            e[j] = ev;
            se += ev;
            su += ev * (u_base + (float)j);
        }
        float* dst = soft + (size_t)(b * N_ + n) * HW_ + m0 + tx * 8;
        ((float4*)dst)[0] = make_float4(e[0], e[1], e[2], e[3]);
        ((float4*)dst)[1] = make_float4(e[4], e[5], e[6], e[7]);
        // reduce across the 16 lanes (one 16-lane group per row)
#pragma unroll
        for (int off = 8; off; off >>= 1) {
            se += __shfl_down_sync(0xffffffffu, se, off, 16);
            su += __shfl_down_sync(0xffffffffu, su, off, 16);
        }
        if (tx == 0) { g_pe[b][n][mt] = se; g_pu[b][n][mt] = su; }
    }
}

// ---------------------------------------------------------------------------
// Per-row reduction over 512 m-tile partials -> denom, pseudo coords
// ---------------------------------------------------------------------------
__global__ void k_reduce(float* __restrict__ out) {
    const int row = blockIdx.x;            // 0..2047
    const int b = row >> 9, n = row & (N_ - 1);
    const int t = threadIdx.x;             // 128 threads
    float se = 0.f, su = 0.f, sv = 0.f;
    for (int mtile = t; mtile < MT_; mtile += 128) {
        float e = g_pe[b][n][mtile];
        float u = g_pu[b][n][mtile];
        se += e; su += u;
        sv += e * (float)(mtile >> 1);     // v = (mtile*128)>>8, constant per tile
    }
    __shared__ float s0[128], s1[128], s2[128];
    s0[t] = se; s1[t] = su; s2[t] = sv;
    __syncthreads();
    for (int off = 64; off; off >>= 1) {
        if (t < off) { s0[t] += s0[t + off]; s1[t] += s1[t + off]; s2[t] += s2[t + off]; }
        __syncthreads();
    }
    if (t == 0) {
        float d = s0[0];
        float u = s1[0] / d, v = s2[0] / d;
        out[row * 2]     = u;
        out[row * 2 + 1] = v;
        g_red[b][n][0] = 1.f / d;
        g_red[b][n][1] = u;
        g_red[b][n][2] = v;
    }
}

// ---------------------------------------------------------------------------
// Scale stored e by 1/denom (in place in the output soft region)
// ---------------------------------------------------------------------------
__global__ void k_scale(float* __restrict__ out) {
    size_t tid = (size_t)blockIdx.x * blockDim.x + threadIdx.x;
    size_t e0 = tid * 4;                               // 4 floats per thread
    int row = (int)(e0 >> 16);                         // 65536 floats per row
    float inv = g_red[row >> 9][row & (N_ - 1)][0];
    float4* p = (float4*)(out + OUT_SOFT + e0);
    float4 v = *p;
    v.x *= inv; v.y *= inv; v.z *= inv; v.w *= inv;
    *p = v;
}

// ---------------------------------------------------------------------------
// Tail: bilinear grid-sample of scores + descriptors at pseudo coords,
// descriptor match score, match weights. One warp per (b, n).
// ---------------------------------------------------------------------------
__global__ void k_tail(const float* __restrict__ kp_scores,
                       const float* __restrict__ scores_dense,
                       const float* __restrict__ desc_dense,
                       float* __restrict__ out) {
    const int warp = (blockIdx.x * blockDim.x + threadIdx.x) >> 5;  // 0..2047
    const int lane = threadIdx.x & 31;
    const int b = warp >> 9, n = warp & (N_ - 1);

    const float u = g_red[b][n][1], v = g_red[b][n][2];
    const float un = 2.f * u / (float)(W_ - 1) - 1.f;
    const float vn = 2.f * v / (float)(H_ - 1) - 1.f;
    const float x = ((un + 1.f) * (float)W_ - 1.f) * 0.5f;
    const float y = ((vn + 1.f) * (float)H_ - 1.f) * 0.5f;
    const float x0f = floorf(x), y0f = floorf(y);
    const float wx1 = x - x0f, wy1 = y - y0f;

    float wts[4] = { (1.f - wx1) * (1.f - wy1), wx1 * (1.f - wy1),
                     (1.f - wx1) * wy1,         wx1 * wy1 };
    float xs[4] = { x0f, x0f + 1.f, x0f,       x0f + 1.f };
    float ys[4] = { y0f, y0f,       y0f + 1.f, y0f + 1.f };
    int   idxc[4];
    float wv[4];
#pragma unroll
    for (int k = 0; k < 4; ++k) {
        bool valid = (xs[k] >= 0.f) && (xs[k] <= (float)(W_ - 1)) &&
                     (ys[k] >= 0.f) && (ys[k] <= (float)(H_ - 1));
        int xi = (int)fminf(fmaxf(xs[k], 0.f), (float)(W_ - 1));
        int yi = (int)fminf(fmaxf(ys[k], 0.f), (float)(H_ - 1));
        idxc[k] = yi * W_ + xi;
        wv[k] = valid ? wts[k] : 0.f;
    }

    const float* sd = scores_dense + (size_t)(2 * b + 1) * HW_;
    float psc = sd[idxc[0]] * wv[0] + sd[idxc[1]] * wv[1] +
                sd[idxc[2]] * wv[2] + sd[idxc[3]] * wv[3];

    const float* dd = desc_dense + (size_t)(2 * b + 1) * C_ * HW_;
    float dot = 0.f;
    for (int c = lane; c < C_; c += 32) {
        const float* dc = dd + (size_t)c * HW_;
        float pd = dc[idxc[0]] * wv[0] + dc[idxc[1]] * wv[1] +
                   dc[idxc[2]] * wv[2] + dc[idxc[3]] * wv[3];
        dot += g_src[b][c][n] * pd;
    }
#pragma unroll
    for (int off = 16; off; off >>= 1)
        dot += __shfl_down_sync(0xffffffffu, dot, off);

    if (lane == 0) {
        float dms = dot / (float)C_;
        float mw = 0.5f * (dms + 1.f) * kp_scores[(size_t)(2 * b) * N_ + n] * psc;
        out[OUT_MW + b * N_ + n] = mw;
    }
}

// ---------------------------------------------------------------------------
extern "C" void kernel_launch(void* const* d_in, const int* in_sizes, int n_in,
                              void* d_out, int out_size) {
    const float* kp_scores    = (const float*)d_in[0];
    const float* kp_desc      = (const float*)d_in[1];
    const float* scores_dense = (const float*)d_in[2];
    const float* desc_dense   = (const float*)d_in[3];
    float* out = (float*)d_out;

    k_norm_kp<<<(B_ * N_ + 255) / 256, 256>>>(kp_desc);
    k_invn<<<(B_ * HW_) / 256, 256>>>(desc_dense);

    dim3 g(4, MT_, B_);
    k_gemm<<<g, 256>>>(desc_dense, out);

    k_reduce<<<B_ * N_, 128>>>(out);
    k_scale<<<(size_t)B_ * N_ * HW_ / (4 * 256), 256>>>(out);
    k_tail<<<(B_ * N_) / 8, 256>>>(kp_scores, scores_dense, desc_dense, out);
}

// round 3
// speedup vs baseline: 1.3862x; 1.3862x over previous
#include <cuda_runtime.h>
#include <cuda_fp16.h>
#include <math.h>
#include <stdint.h>

// Problem constants: BW=8, WINDOW=2 -> B=4; C=128, N=512, H=W=256
#define B_   4
#define C_   128
#define N_   512
#define H_   256
#define W_   256
#define HW_  65536
#define MT_  512           // number of 128-wide m tiles per row

// Output layout: pseudo_coords (4,512,2) | match_weights (4,1,512) | soft_match (4,512,65536)
#define OUT_MW   (B_ * N_ * 2)
#define OUT_SOFT (B_ * N_ * 2 + B_ * N_)

// ---- device scratch ----
__device__ float g_src[B_][C_][N_];                 // normalized kp desc (fp32, for tail)
__device__ float g_pe[B_][N_][MT_];                 // partial sum e
__device__ float g_pu[B_][N_][MT_];                 // partial sum e*u
__device__ float g_red[B_][N_][3];                  // inv_denom, u, v
__device__ __half g_ah[B_ * N_ * C_];               // src hi   [b][n][c]
__device__ __half g_al[B_ * N_ * C_];               // src lo
__device__ __half g_bh[(size_t)B_ * HW_ * C_];      // dense hi [b][m][c] (normalized)
__device__ __half g_bl[(size_t)B_ * HW_ * C_];      // dense lo

// ===========================================================================
// asm helpers
// ===========================================================================
__device__ __forceinline__ uint32_t smem_u32(const void* p) {
    uint32_t a;
    asm("{ .reg .u64 t; cvta.to.shared.u64 t, %1; cvt.u32.u64 %0, t; }" : "=r"(a) : "l"(p));
    return a;
}
__device__ __forceinline__ uint64_t gmem_u64(const void* p) {
    uint64_t g;
    asm("cvta.to.global.u64 %0, %1;" : "=l"(g) : "l"(p));
    return g;
}
#define CP_ASYNC16(sm, gp) \
    asm volatile("cp.async.cg.shared.global [%0], [%1], 16;" :: "r"(sm), "l"(gp) : "memory")
#define CP_COMMIT() asm volatile("cp.async.commit_group;" ::: "memory")
#define CP_WAIT(n)  asm volatile("cp.async.wait_group %0;" :: "n"(n) : "memory")

#define LDSM_X4(r0, r1, r2, r3, addr) \
    asm volatile("ldmatrix.sync.aligned.m8n8.x4.shared.b16 {%0,%1,%2,%3}, [%4];" \
                 : "=r"(r0), "=r"(r1), "=r"(r2), "=r"(r3) : "r"(addr))

#define MMA16816(d, a0, a1, a2, a3, b0, b1) \
    asm volatile("mma.sync.aligned.m16n8k16.row.col.f32.f16.f16.f32 " \
                 "{%0,%1,%2,%3}, {%4,%5,%6,%7}, {%8,%9}, {%0,%1,%2,%3};" \
                 : "+f"((d)[0]), "+f"((d)[1]), "+f"((d)[2]), "+f"((d)[3]) \
                 : "r"(a0), "r"(a1), "r"(a2), "r"(a3), "r"(b0), "r"(b1))

// padded smem layout: 128 rows x 128 halfs, row stride 272 B (17 x 16B, conflict-free)
#define ROWB 272
#define TILE_SM (128 * ROWB)     // 34816 B
#define SM_AH 0
#define SM_AL TILE_SM
#define SM_BH (2 * TILE_SM)
#define SM_BL (3 * TILE_SM)
#define GEMM_SMEM (4 * TILE_SM)  // 139264 B

// ===========================================================================
// Prep: normalize keypoint descriptors -> g_src (fp32) + g_ah/g_al (fp16 hi/lo)
// ===========================================================================
__global__ void k_prep_src(const float* __restrict__ kp_desc) {
    int t = blockIdx.x * blockDim.x + threadIdx.x;
    if (t >= B_ * N_) return;
    int b = t / N_, n = t - b * N_;
    const float* src = kp_desc + (size_t)(2 * b) * C_ * N_ + n;
    float s = 0.f;
#pragma unroll 8
    for (int c = 0; c < C_; ++c) { float v = src[(size_t)c * N_]; s += v * v; }
    float inv = 1.f / fmaxf(sqrtf(s), 1e-12f);
#pragma unroll 8
    for (int c = 0; c < C_; ++c) {
        float x = src[(size_t)c * N_] * inv;
        g_src[b][c][n] = x;
        __half h = __float2half_rn(x);
        g_ah[(size_t)(b * N_ + n) * C_ + c] = h;
        g_al[(size_t)(b * N_ + n) * C_ + c] = __float2half_rn(x - __half2float(h));
    }
}

// ===========================================================================
// Prep: normalize dense map (single read), split fp16 hi/lo, write transposed
// [b][m][c]. block = 128 m columns; thread t: m = t&127, c-half = t>>7.
// ===========================================================================
__global__ void __launch_bounds__(256) k_prep_dense(const float* __restrict__ dense) {
    __shared__ float s_ps[2][128];
    const int m_loc = threadIdx.x & 127, half = threadIdx.x >> 7;
    const int m = blockIdx.x * 128 + m_loc;
    const int b = blockIdx.y;
    const float* base = dense + (size_t)(2 * b + 1) * C_ * HW_ + m;

    float v[64];
    float s = 0.f;
#pragma unroll
    for (int i = 0; i < 64; ++i) {
        v[i] = base[(size_t)(half * 64 + i) * HW_];
        s += v[i] * v[i];
    }
    s_ps[half][m_loc] = s;
    __syncthreads();
    float inv = 1.f / fmaxf(sqrtf(s_ps[0][m_loc] + s_ps[1][m_loc]), 1e-12f);

    __half* oh = g_bh + ((size_t)b * HW_ + m) * C_ + half * 64;
    __half* ol = g_bl + ((size_t)b * HW_ + m) * C_ + half * 64;
#pragma unroll
    for (int ch = 0; ch < 8; ++ch) {
        __half hh[8], ll[8];
#pragma unroll
        for (int j = 0; j < 8; ++j) {
            float x = v[ch * 8 + j] * inv;
            hh[j] = __float2half_rn(x);
            ll[j] = __float2half_rn(x - __half2float(hh[j]));
        }
        *(float4*)(oh + ch * 8) = *(float4*)hh;
        *(float4*)(ol + ch * 8) = *(float4*)ll;
    }
}

// ===========================================================================
// Tensor-core GEMM (mma.sync fp16 hi/lo split) + fused exp epilogue.
// CTA: 128 n-rows x 128 m-cols, K=128. grid (nt=4, mc=512, b=4).
// Writes unnormalized e = exp(100*cos) + per-(row, mtile) partials.
// ===========================================================================
__device__ __forceinline__ void product128(uint32_t sbA, uint32_t sbB,
                                           float acc[4][4][4],
                                           uint32_t aoff, uint32_t boff) {
#pragma unroll
    for (int ks = 0; ks < 8; ++ks) {
        const uint32_t kb = ks * 32;
        uint32_t a[4][4], bf[2][4];
#pragma unroll
        for (int Mi = 0; Mi < 4; ++Mi)
            LDSM_X4(a[Mi][0], a[Mi][1], a[Mi][2], a[Mi][3],
                    sbA + aoff + Mi * (16 * ROWB) + kb);
#pragma unroll
        for (int pr = 0; pr < 2; ++pr)
            LDSM_X4(bf[pr][0], bf[pr][1], bf[pr][2], bf[pr][3],
                    sbB + boff + pr * (16 * ROWB) + kb);
#pragma unroll
        for (int Mi = 0; Mi < 4; ++Mi)
#pragma unroll
            for (int Nj = 0; Nj < 4; ++Nj)
                MMA16816(acc[Mi][Nj], a[Mi][0], a[Mi][1], a[Mi][2], a[Mi][3],
                         bf[Nj >> 1][(Nj & 1) * 2], bf[Nj >> 1][(Nj & 1) * 2 + 1]);
    }
}

__global__ void __launch_bounds__(256, 1) k_mma(float* __restrict__ out) {
    extern __shared__ char dyn[];
    __shared__ float s_red[128][4][2];
    const uint32_t sb = smem_u32(dyn);
    const int nt = blockIdx.x, mc = blockIdx.y, b = blockIdx.z;
    const int n0 = nt * 128;
    const int tid = threadIdx.x, lane = tid & 31, wid = tid >> 5;
    const int warpM = wid & 1, warpN = wid >> 1;

    // ---- stage smem via cp.async ----
    const uint64_t Agh = gmem_u64(g_ah + (size_t)(b * N_ + n0) * C_);
    const uint64_t Agl = gmem_u64(g_al + (size_t)(b * N_ + n0) * C_);
    const uint64_t Bgh = gmem_u64(g_bh + ((size_t)b * HW_ + (size_t)mc * 128) * C_);
    const uint64_t Bgl = gmem_u64(g_bl + ((size_t)b * HW_ + (size_t)mc * 128) * C_);
#pragma unroll
    for (int i = 0; i < 8; ++i) {
        const uint32_t f = tid + 256 * i;
        const uint32_t r = f >> 4, cB = (f & 15) * 16;   // byte offset within row
        const uint32_t d = r * ROWB + cB;
        CP_ASYNC16(sb + SM_BH + d, Bgh + r * 256 + cB);
        CP_ASYNC16(sb + SM_AH + d, Agh + r * 256 + cB);
        CP_ASYNC16(sb + SM_AL + d, Agl + r * 256 + cB);
    }
    CP_COMMIT();
#pragma unroll
    for (int i = 0; i < 8; ++i) {
        const uint32_t f = tid + 256 * i;
        const uint32_t r = f >> 4, cB = (f & 15) * 16;
        CP_ASYNC16(sb + SM_BL + r * ROWB + cB, Bgl + r * 256 + cB);
    }
    CP_COMMIT();

    float acc[4][4][4];
#pragma unroll
    for (int Mi = 0; Mi < 4; ++Mi)
#pragma unroll
        for (int Nj = 0; Nj < 4; ++Nj)
#pragma unroll
            for (int q = 0; q < 4; ++q) acc[Mi][Nj][q] = 0.f;

    // per-thread ldmatrix base offsets
    const uint32_t aoff = (warpM * 64 + (lane & 15)) * ROWB + ((lane >> 4) << 4);
    const uint32_t boff = (warpN * 32 + (lane & 7) + ((lane >> 4) << 3)) * ROWB +
                          (((lane >> 3) & 1) << 4);

    CP_WAIT(1);           // Ah, Al, Bh ready
    __syncthreads();
    product128(sb + SM_AH, sb + SM_BH, acc, aoff, boff);   // ah*bh
    product128(sb + SM_AL, sb + SM_BH, acc, aoff, boff);   // al*bh
    CP_WAIT(0);           // Bl ready
    __syncthreads();
    product128(sb + SM_AH, sb + SM_BL, acc, aoff, boff);   // ah*bl

    // ---- epilogue: exp, store e, per-row partials ----
    const int rbase = warpM * 64 + (lane >> 2);
    const int cbase = warpN * 32 + 2 * (lane & 3);
    const float u0 = (float)(((mc & 1) << 7) + cbase);
    float* osoft = out + OUT_SOFT;
#pragma unroll
    for (int Mi = 0; Mi < 4; ++Mi) {
        const int R0 = rbase + Mi * 16, R1 = R0 + 8;
        float* p0 = osoft + (size_t)(b * N_ + n0 + R0) * HW_ + mc * 128 + cbase;
        float* p1 = osoft + (size_t)(b * N_ + n0 + R1) * HW_ + mc * 128 + cbase;
        float se0 = 0.f, su0 = 0.f, se1 = 0.f, su1 = 0.f;
#pragma unroll
        for (int Nj = 0; Nj < 4; ++Nj) {
            float e00 = __expf(100.f * acc[Mi][Nj][0]);
            float e01 = __expf(100.f * acc[Mi][Nj][1]);
            float e10 = __expf(100.f * acc[Mi][Nj][2]);
            float e11 = __expf(100.f * acc[Mi][Nj][3]);
            *(float2*)(p0 + Nj * 8) = make_float2(e00, e01);
            *(float2*)(p1 + Nj * 8) = make_float2(e10, e11);
            const float uu = u0 + (float)(Nj * 8);
            se0 += e00 + e01; su0 += e00 * uu + e01 * (uu + 1.f);
            se1 += e10 + e11; su1 += e10 * uu + e11 * (uu + 1.f);
        }
#pragma unroll
        for (int msk = 1; msk <= 2; msk <<= 1) {
            se0 += __shfl_xor_sync(0xffffffffu, se0, msk);
            su0 += __shfl_xor_sync(0xffffffffu, su0, msk);
            se1 += __shfl_xor_sync(0xffffffffu, se1, msk);
            su1 += __shfl_xor_sync(0xffffffffu, su1, msk);
        }
        if ((lane & 3) == 0) {
            s_red[R0][warpN][0] = se0; s_red[R0][warpN][1] = su0;
            s_red[R1][warpN][0] = se1; s_red[R1][warpN][1] = su1;
        }
    }
    __syncthreads();
    if (tid < 128) {
        float se = s_red[tid][0][0] + s_red[tid][1][0] + s_red[tid][2][0] + s_red[tid][3][0];
        float su = s_red[tid][0][1] + s_red[tid][1][1] + s_red[tid][2][1] + s_red[tid][3][1];
        g_pe[b][n0 + tid][mc] = se;
        g_pu[b][n0 + tid][mc] = su;
    }
}

// ===========================================================================
// Per-row reduction over 512 m-tile partials -> denom, pseudo coords
// ===========================================================================
__global__ void k_reduce(float* __restrict__ out) {
    const int row = blockIdx.x;            // 0..2047
    const int b = row >> 9, n = row & (N_ - 1);
    const int t = threadIdx.x;             // 128 threads
    float se = 0.f, su = 0.f, sv = 0.f;
    for (int mtile = t; mtile < MT_; mtile += 128) {
        float e = g_pe[b][n][mtile];
        float u = g_pu[b][n][mtile];
        se += e; su += u;
        sv += e * (float)(mtile >> 1);
    }
    __shared__ float s0[128], s1[128], s2[128];
    s0[t] = se; s1[t] = su; s2[t] = sv;
    __syncthreads();
    for (int off = 64; off; off >>= 1) {
        if (t < off) { s0[t] += s0[t + off]; s1[t] += s1[t + off]; s2[t] += s2[t + off]; }
        __syncthreads();
    }
    if (t == 0) {
        float d = s0[0];
        float u = s1[0] / d, v = s2[0] / d;
        out[row * 2]     = u;
        out[row * 2 + 1] = v;
        g_red[b][n][0] = 1.f / d;
        g_red[b][n][1] = u;
        g_red[b][n][2] = v;
    }
}

// ===========================================================================
// Scale stored e by 1/denom (in place in the output soft region)
// ===========================================================================
__global__ void k_scale(float* __restrict__ out) {
    size_t tid = (size_t)blockIdx.x * blockDim.x + threadIdx.x;
    size_t e0 = tid * 4;
    int row = (int)(e0 >> 16);
    float inv = g_red[row >> 9][row & (N_ - 1)][0];
    float4* p = (float4*)(out + OUT_SOFT + e0);
    float4 v = *p;
    v.x *= inv; v.y *= inv; v.z *= inv; v.w *= inv;
    *p = v;
}

// ===========================================================================
// Tail: bilinear grid-sample + match weights (one warp per (b,n))
// ===========================================================================
__global__ void k_tail(const float* __restrict__ kp_scores,
                       const float* __restrict__ scores_dense,
                       const float* __restrict__ desc_dense,
                       float* __restrict__ out) {
    const int warp = (blockIdx.x * blockDim.x + threadIdx.x) >> 5;
    const int lane = threadIdx.x & 31;
    const int b = warp >> 9, n = warp & (N_ - 1);

    const float u = g_red[b][n][1], v = g_red[b][n][2];
    const float un = 2.f * u / (float)(W_ - 1) - 1.f;
    const float vn = 2.f * v / (float)(H_ - 1) - 1.f;
    const float x = ((un + 1.f) * (float)W_ - 1.f) * 0.5f;
    const float y = ((vn + 1.f) * (float)H_ - 1.f) * 0.5f;
    const float x0f = floorf(x), y0f = floorf(y);
    const float wx1 = x - x0f, wy1 = y - y0f;

    float wts[4] = { (1.f - wx1) * (1.f - wy1), wx1 * (1.f - wy1),
                     (1.f - wx1) * wy1,         wx1 * wy1 };
    float xs[4] = { x0f, x0f + 1.f, x0f,       x0f + 1.f };
    float ys[4] = { y0f, y0f,       y0f + 1.f, y0f + 1.f };
    int   idxc[4];
    float wv[4];
#pragma unroll
    for (int k = 0; k < 4; ++k) {
        bool valid = (xs[k] >= 0.f) && (xs[k] <= (float)(W_ - 1)) &&
                     (ys[k] >= 0.f) && (ys[k] <= (float)(H_ - 1));
        int xi = (int)fminf(fmaxf(xs[k], 0.f), (float)(W_ - 1));
        int yi = (int)fminf(fmaxf(ys[k], 0.f), (float)(H_ - 1));
        idxc[k] = yi * W_ + xi;
        wv[k] = valid ? wts[k] : 0.f;
    }

    const float* sd = scores_dense + (size_t)(2 * b + 1) * HW_;
    float psc = sd[idxc[0]] * wv[0] + sd[idxc[1]] * wv[1] +
                sd[idxc[2]] * wv[2] + sd[idxc[3]] * wv[3];

    const float* dd = desc_dense + (size_t)(2 * b + 1) * C_ * HW_;
    float dot = 0.f;
    for (int c = lane; c < C_; c += 32) {
        const float* dc = dd + (size_t)c * HW_;
        float pd = dc[idxc[0]] * wv[0] + dc[idxc[1]] * wv[1] +
                   dc[idxc[2]] * wv[2] + dc[idxc[3]] * wv[3];
        dot += g_src[b][c][n] * pd;
    }
#pragma unroll
    for (int off = 16; off; off >>= 1)
        dot += __shfl_down_sync(0xffffffffu, dot, off);

    if (lane == 0) {
        float dms = dot / (float)C_;
        float mw = 0.5f * (dms + 1.f) * kp_scores[(size_t)(2 * b) * N_ + n] * psc;
        out[OUT_MW + b * N_ + n] = mw;
    }
}

// ===========================================================================
extern "C" void kernel_launch(void* const* d_in, const int* in_sizes, int n_in,
                              void* d_out, int out_size) {
    const float* kp_scores    = (const float*)d_in[0];
    const float* kp_desc      = (const float*)d_in[1];
    const float* scores_dense = (const float*)d_in[2];
    const float* desc_dense   = (const float*)d_in[3];
    float* out = (float*)d_out;

    cudaFuncSetAttribute(k_mma, cudaFuncAttributeMaxDynamicSharedMemorySize, GEMM_SMEM);

    k_prep_src<<<(B_ * N_ + 255) / 256, 256>>>(kp_desc);
    {
        dim3 gp(HW_ / 128, B_);
        k_prep_dense<<<gp, 256>>>(desc_dense);
    }
    {
        dim3 gg(4, MT_, B_);
        k_mma<<<gg, 256, GEMM_SMEM>>>(out);
    }
    k_reduce<<<B_ * N_, 128>>>(out);
    k_scale<<<(size_t)B_ * N_ * HW_ / (4 * 256), 256>>>(out);
    k_tail<<<(B_ * N_) / 8, 256>>>(kp_scores, scores_dense, desc_dense, out);
}

// round 4
// speedup vs baseline: 1.4167x; 1.0220x over previous
#include <cuda_runtime.h>
#include <cuda_fp16.h>
#include <math.h>
#include <stdint.h>

// Problem constants: BW=8, WINDOW=2 -> B=4; C=128, N=512, H=W=256
#define B_   4
#define C_   128
#define N_   512
#define H_   256
#define W_   256
#define HW_  65536
#define MT_  512           // number of 128-wide m tiles per row

// Output layout: pseudo_coords (4,512,2) | match_weights (4,1,512) | soft_match (4,512,65536)
#define OUT_MW   (B_ * N_ * 2)
#define OUT_SOFT (B_ * N_ * 2 + B_ * N_)

// ---- device scratch ----
__device__ float g_src[B_][C_][N_];                 // normalized kp desc (fp32, for tail)
__device__ float g_pe[B_][N_][MT_];                 // partial sum e
__device__ float g_pu[B_][N_][MT_];                 // partial sum e*u
__device__ float g_red[B_][N_][3];                  // inv_denom, u, v
__device__ __half g_ah[B_ * N_ * C_];               // src hi   [b][n][c]
__device__ __half g_al[B_ * N_ * C_];               // src lo
__device__ __half g_bh[(size_t)B_ * HW_ * C_];      // dense hi [b][m][c] (normalized)
__device__ __half g_bl[(size_t)B_ * HW_ * C_];      // dense lo

// ===========================================================================
// asm helpers
// ===========================================================================
__device__ __forceinline__ uint32_t smem_u32(const void* p) {
    uint32_t a;
    asm("{ .reg .u64 t; cvta.to.shared.u64 t, %1; cvt.u32.u64 %0, t; }" : "=r"(a) : "l"(p));
    return a;
}
__device__ __forceinline__ uint64_t gmem_u64(const void* p) {
    uint64_t g;
    asm("cvta.to.global.u64 %0, %1;" : "=l"(g) : "l"(p));
    return g;
}
#define CP_ASYNC16(sm, gp) \
    asm volatile("cp.async.cg.shared.global [%0], [%1], 16;" :: "r"(sm), "l"(gp) : "memory")
#define CP_COMMIT() asm volatile("cp.async.commit_group;" ::: "memory")
#define CP_WAIT(n)  asm volatile("cp.async.wait_group %0;" :: "n"(n) : "memory")

#define LDSM_X4(r0, r1, r2, r3, addr) \
    asm volatile("ldmatrix.sync.aligned.m8n8.x4.shared.b16 {%0,%1,%2,%3}, [%4];" \
                 : "=r"(r0), "=r"(r1), "=r"(r2), "=r"(r3) : "r"(addr))

#define MMA16816(d, a0, a1, a2, a3, b0, b1) \
    asm volatile("mma.sync.aligned.m16n8k16.row.col.f32.f16.f16.f32 " \
                 "{%0,%1,%2,%3}, {%4,%5,%6,%7}, {%8,%9}, {%0,%1,%2,%3};" \
                 : "+f"((d)[0]), "+f"((d)[1]), "+f"((d)[2]), "+f"((d)[3]) \
                 : "r"(a0), "r"(a1), "r"(a2), "r"(a3), "r"(b0), "r"(b1))

// padded smem layout: 128 rows x 128 halfs, row stride 272 B (17 x 16B)
#define ROWB 272
#define TILE_SM (128 * ROWB)     // 34816 B
#define SM_AH 0
#define SM_X  TILE_SM            // holds Al, then Bl
#define SM_BH (2 * TILE_SM)
#define GEMM_SMEM (3 * TILE_SM)  // 104448 B -> 2 CTAs/SM

// ===========================================================================
// Prep: normalize keypoint descriptors -> g_src (fp32) + g_ah/g_al (fp16 hi/lo)
// ===========================================================================
__global__ void k_prep_src(const float* __restrict__ kp_desc) {
    int t = blockIdx.x * blockDim.x + threadIdx.x;
    if (t >= B_ * N_) return;
    int b = t / N_, n = t - b * N_;
    const float* src = kp_desc + (size_t)(2 * b) * C_ * N_ + n;
    float s = 0.f;
#pragma unroll 8
    for (int c = 0; c < C_; ++c) { float v = src[(size_t)c * N_]; s += v * v; }
    float inv = 1.f / fmaxf(sqrtf(s), 1e-12f);
#pragma unroll 8
    for (int c = 0; c < C_; ++c) {
        float x = src[(size_t)c * N_] * inv;
        g_src[b][c][n] = x;
        __half h = __float2half_rn(x);
        g_ah[(size_t)(b * N_ + n) * C_ + c] = h;
        g_al[(size_t)(b * N_ + n) * C_ + c] = __float2half_rn(x - __half2float(h));
    }
}

// ===========================================================================
// Prep: normalize dense map, split fp16 hi/lo, write transposed [b][m][c].
// v3: smem-staged transpose -> coalesced global reads AND writes.
// dynamic smem: 128 x 132 floats (+128 inv) = 68.1 KB
// ===========================================================================
#define PREP_SMEM (128 * 132 * 4 + 128 * 4)
__global__ void __launch_bounds__(256) k_prep_dense(const float* __restrict__ dense) {
    extern __shared__ float s_dyn[];
    float (*s_raw)[132] = (float (*)[132])s_dyn;
    float* s_inv = s_dyn + 128 * 132;
    const int m0 = blockIdx.x * 128, b = blockIdx.y;
    const int t = threadIdx.x;
    const float* base = dense + (size_t)(2 * b + 1) * C_ * HW_ + m0;

    // coalesced read of 128c x 128m tile, transposed store into smem
#pragma unroll
    for (int i = 0; i < 16; ++i) {
        int f = t + 256 * i;              // 0..4095 float4 units
        int c = f >> 5, m4 = (f & 31) * 4;
        float4 v = *(const float4*)(base + (size_t)c * HW_ + m4);
        s_raw[m4 + 0][c] = v.x;
        s_raw[m4 + 1][c] = v.y;
        s_raw[m4 + 2][c] = v.z;
        s_raw[m4 + 3][c] = v.w;
    }
    __syncthreads();
    if (t < 128) {
        float s = 0.f;
#pragma unroll 16
        for (int c = 0; c < 128; ++c) { float v = s_raw[t][c]; s += v * v; }
        s_inv[t] = 1.f / fmaxf(sqrtf(s), 1e-12f);
    }
    __syncthreads();

    // coalesced write: half-warp per m row (lane -> c), 8 rows per thread
    const int mloc = t >> 4, cb = (t & 15) * 8;
#pragma unroll
    for (int it = 0; it < 8; ++it) {
        int m = it * 16 + mloc;
        float inv = s_inv[m];
        __half hh[8], ll[8];
#pragma unroll
        for (int j = 0; j < 8; ++j) {
            float x = s_raw[m][cb + j] * inv;
            hh[j] = __float2half_rn(x);
            ll[j] = __float2half_rn(x - __half2float(hh[j]));
        }
        size_t off = ((size_t)b * HW_ + m0 + m) * C_ + cb;
        *(float4*)(g_bh + off) = *(float4*)hh;
        *(float4*)(g_bl + off) = *(float4*)ll;
    }
}

// ===========================================================================
// Tensor-core GEMM (mma.sync fp16 hi/lo split) + fused exp epilogue.
// CTA: 128 n-rows x 128 m-cols, K=128. grid (nt=4, mc=512, b=4).
// 3 smem buffers (Ah, X=Al->Bl, Bh) -> 104 KB -> 2 CTAs/SM for phase overlap.
// ===========================================================================
__device__ __forceinline__ void product128(uint32_t sbA, uint32_t sbB,
                                           float acc[4][4][4],
                                           uint32_t aoff, uint32_t boff) {
#pragma unroll
    for (int ks = 0; ks < 8; ++ks) {
        const uint32_t kb = ks * 32;
        uint32_t a[4][4], bf[2][4];
#pragma unroll
        for (int Mi = 0; Mi < 4; ++Mi)
            LDSM_X4(a[Mi][0], a[Mi][1], a[Mi][2], a[Mi][3],
                    sbA + aoff + Mi * (16 * ROWB) + kb);
#pragma unroll
        for (int pr = 0; pr < 2; ++pr)
            LDSM_X4(bf[pr][0], bf[pr][1], bf[pr][2], bf[pr][3],
                    sbB + boff + pr * (16 * ROWB) + kb);
#pragma unroll
        for (int Mi = 0; Mi < 4; ++Mi)
#pragma unroll
            for (int Nj = 0; Nj < 4; ++Nj)
                MMA16816(acc[Mi][Nj], a[Mi][0], a[Mi][1], a[Mi][2], a[Mi][3],
                         bf[Nj >> 1][(Nj & 1) * 2], bf[Nj >> 1][(Nj & 1) * 2 + 1]);
    }
}

__global__ void __launch_bounds__(256, 2) k_mma(float* __restrict__ out) {
    extern __shared__ char dyn[];
    __shared__ float s_red[128][4][2];
    const uint32_t sb = smem_u32(dyn);
    const int nt = blockIdx.x, mc = blockIdx.y, b = blockIdx.z;
    const int n0 = nt * 128;
    const int tid = threadIdx.x, lane = tid & 31, wid = tid >> 5;
    const int warpM = wid & 1, warpN = wid >> 1;

    // ---- stage Ah, Al(->X), Bh via cp.async ----
    const uint64_t Agh = gmem_u64(g_ah + (size_t)(b * N_ + n0) * C_);
    const uint64_t Agl = gmem_u64(g_al + (size_t)(b * N_ + n0) * C_);
    const uint64_t Bgh = gmem_u64(g_bh + ((size_t)b * HW_ + (size_t)mc * 128) * C_);
    const uint64_t Bgl = gmem_u64(g_bl + ((size_t)b * HW_ + (size_t)mc * 128) * C_);
#pragma unroll
    for (int i = 0; i < 8; ++i) {
        const uint32_t f = tid + 256 * i;
        const uint32_t r = f >> 4, cB = (f & 15) * 16;   // byte offset within row
        const uint32_t d = r * ROWB + cB;
        CP_ASYNC16(sb + SM_BH + d, Bgh + r * 256 + cB);
        CP_ASYNC16(sb + SM_AH + d, Agh + r * 256 + cB);
        CP_ASYNC16(sb + SM_X  + d, Agl + r * 256 + cB);
    }
    CP_COMMIT();

    float acc[4][4][4];
#pragma unroll
    for (int Mi = 0; Mi < 4; ++Mi)
#pragma unroll
        for (int Nj = 0; Nj < 4; ++Nj)
#pragma unroll
            for (int q = 0; q < 4; ++q) acc[Mi][Nj][q] = 0.f;

    // per-thread ldmatrix base offsets
    const uint32_t aoff = (warpM * 64 + (lane & 15)) * ROWB + ((lane >> 4) << 4);
    const uint32_t boff = (warpN * 32 + (lane & 7) + ((lane >> 4) << 3)) * ROWB +
                          (((lane >> 3) & 1) << 4);

    CP_WAIT(0);
    __syncthreads();
    product128(sb + SM_AH, sb + SM_BH, acc, aoff, boff);   // ah*bh
    product128(sb + SM_X,  sb + SM_BH, acc, aoff, boff);   // al*bh
    __syncthreads();                                       // everyone done reading X
#pragma unroll
    for (int i = 0; i < 8; ++i) {
        const uint32_t f = tid + 256 * i;
        const uint32_t r = f >> 4, cB = (f & 15) * 16;
        CP_ASYNC16(sb + SM_X + r * ROWB + cB, Bgl + r * 256 + cB);
    }
    CP_COMMIT();
    CP_WAIT(0);
    __syncthreads();
    product128(sb + SM_AH, sb + SM_X, acc, aoff, boff);    // ah*bl

    // ---- epilogue: exp, store e, per-row partials ----
    const int rbase = warpM * 64 + (lane >> 2);
    const int cbase = warpN * 32 + 2 * (lane & 3);
    const float u0 = (float)(((mc & 1) << 7) + cbase);
    float* osoft = out + OUT_SOFT;
#pragma unroll
    for (int Mi = 0; Mi < 4; ++Mi) {
        const int R0 = rbase + Mi * 16, R1 = R0 + 8;
        float* p0 = osoft + (size_t)(b * N_ + n0 + R0) * HW_ + mc * 128 + cbase;
        float* p1 = osoft + (size_t)(b * N_ + n0 + R1) * HW_ + mc * 128 + cbase;
        float se0 = 0.f, su0 = 0.f, se1 = 0.f, su1 = 0.f;
#pragma unroll
        for (int Nj = 0; Nj < 4; ++Nj) {
            float e00 = __expf(100.f * acc[Mi][Nj][0]);
            float e01 = __expf(100.f * acc[Mi][Nj][1]);
            float e10 = __expf(100.f * acc[Mi][Nj][2]);
            float e11 = __expf(100.f * acc[Mi][Nj][3]);
            *(float2*)(p0 + Nj * 8) = make_float2(e00, e01);
            *(float2*)(p1 + Nj * 8) = make_float2(e10, e11);
            const float uu = u0 + (float)(Nj * 8);
            se0 += e00 + e01; su0 += e00 * uu + e01 * (uu + 1.f);
            se1 += e10 + e11; su1 += e10 * uu + e11 * (uu + 1.f);
        }
#pragma unroll
        for (int msk = 1; msk <= 2; msk <<= 1) {
            se0 += __shfl_xor_sync(0xffffffffu, se0, msk);
            su0 += __shfl_xor_sync(0xffffffffu, su0, msk);
            se1 += __shfl_xor_sync(0xffffffffu, se1, msk);
            su1 += __shfl_xor_sync(0xffffffffu, su1, msk);
        }
        if ((lane & 3) == 0) {
            s_red[R0][warpN][0] = se0; s_red[R0][warpN][1] = su0;
            s_red[R1][warpN][0] = se1; s_red[R1][warpN][1] = su1;
        }
    }
    __syncthreads();
    if (tid < 128) {
        float se = s_red[tid][0][0] + s_red[tid][1][0] + s_red[tid][2][0] + s_red[tid][3][0];
        float su = s_red[tid][0][1] + s_red[tid][1][1] + s_red[tid][2][1] + s_red[tid][3][1];
        g_pe[b][n0 + tid][mc] = se;
        g_pu[b][n0 + tid][mc] = su;
    }
}

// ===========================================================================
// Per-row reduction over 512 m-tile partials -> denom, pseudo coords
// ===========================================================================
__global__ void k_reduce(float* __restrict__ out) {
    const int row = blockIdx.x;            // 0..2047
    const int b = row >> 9, n = row & (N_ - 1);
    const int t = threadIdx.x;             // 128 threads
    float se = 0.f, su = 0.f, sv = 0.f;
    for (int mtile = t; mtile < MT_; mtile += 128) {
        float e = g_pe[b][n][mtile];
        float u = g_pu[b][n][mtile];
        se += e; su += u;
        sv += e * (float)(mtile >> 1);
    }
    __shared__ float s0[128], s1[128], s2[128];
    s0[t] = se; s1[t] = su; s2[t] = sv;
    __syncthreads();
    for (int off = 64; off; off >>= 1) {
        if (t < off) { s0[t] += s0[t + off]; s1[t] += s1[t + off]; s2[t] += s2[t + off]; }
        __syncthreads();
    }
    if (t == 0) {
        float d = s0[0];
        float u = s1[0] / d, v = s2[0] / d;
        out[row * 2]     = u;
        out[row * 2 + 1] = v;
        g_red[b][n][0] = 1.f / d;
        g_red[b][n][1] = u;
        g_red[b][n][2] = v;
    }
}

// ===========================================================================
// Scale stored e by 1/denom (in place in the output soft region)
// ===========================================================================
__global__ void k_scale(float* __restrict__ out) {
    size_t tid = (size_t)blockIdx.x * blockDim.x + threadIdx.x;
    size_t e0 = tid * 4;
    int row = (int)(e0 >> 16);
    float inv = g_red[row >> 9][row & (N_ - 1)][0];
    float4* p = (float4*)(out + OUT_SOFT + e0);
    float4 v = *p;
    v.x *= inv; v.y *= inv; v.z *= inv; v.w *= inv;
    *p = v;
}

// ===========================================================================
// Tail: bilinear grid-sample + match weights (one warp per (b,n))
// ===========================================================================
__global__ void k_tail(const float* __restrict__ kp_scores,
                       const float* __restrict__ scores_dense,
                       const float* __restrict__ desc_dense,
                       float* __restrict__ out) {
    const int warp = (blockIdx.x * blockDim.x + threadIdx.x) >> 5;
    const int lane = threadIdx.x & 31;
    const int b = warp >> 9, n = warp & (N_ - 1);

    const float u = g_red[b][n][1], v = g_red[b][n][2];
    const float un = 2.f * u / (float)(W_ - 1) - 1.f;
    const float vn = 2.f * v / (float)(H_ - 1) - 1.f;
    const float x = ((un + 1.f) * (float)W_ - 1.f) * 0.5f;
    const float y = ((vn + 1.f) * (float)H_ - 1.f) * 0.5f;
    const float x0f = floorf(x), y0f = floorf(y);
    const float wx1 = x - x0f, wy1 = y - y0f;

    float wts[4] = { (1.f - wx1) * (1.f - wy1), wx1 * (1.f - wy1),
                     (1.f - wx1) * wy1,         wx1 * wy1 };
    float xs[4] = { x0f, x0f + 1.f, x0f,       x0f + 1.f };
    float ys[4] = { y0f, y0f,       y0f + 1.f, y0f + 1.f };
    int   idxc[4];
    float wv[4];
#pragma unroll
    for (int k = 0; k < 4; ++k) {
        bool valid = (xs[k] >= 0.f) && (xs[k] <= (float)(W_ - 1)) &&
                     (ys[k] >= 0.f) && (ys[k] <= (float)(H_ - 1));
        int xi = (int)fminf(fmaxf(xs[k], 0.f), (float)(W_ - 1));
        int yi = (int)fminf(fmaxf(ys[k], 0.f), (float)(H_ - 1));
        idxc[k] = yi * W_ + xi;
        wv[k] = valid ? wts[k] : 0.f;
    }

    const float* sd = scores_dense + (size_t)(2 * b + 1) * HW_;
    float psc = sd[idxc[0]] * wv[0] + sd[idxc[1]] * wv[1] +
                sd[idxc[2]] * wv[2] + sd[idxc[3]] * wv[3];

    const float* dd = desc_dense + (size_t)(2 * b + 1) * C_ * HW_;
    float dot = 0.f;
    for (int c = lane; c < C_; c += 32) {
        const float* dc = dd + (size_t)c * HW_;
        float pd = dc[idxc[0]] * wv[0] + dc[idxc[1]] * wv[1] +
                   dc[idxc[2]] * wv[2] + dc[idxc[3]] * wv[3];
        dot += g_src[b][c][n] * pd;
    }
#pragma unroll
    for (int off = 16; off; off >>= 1)
        dot += __shfl_down_sync(0xffffffffu, dot, off);

    if (lane == 0) {
        float dms = dot / (float)C_;
        float mw = 0.5f * (dms + 1.f) * kp_scores[(size_t)(2 * b) * N_ + n] * psc;
        out[OUT_MW + b * N_ + n] = mw;
    }
}

// ===========================================================================
extern "C" void kernel_launch(void* const* d_in, const int* in_sizes, int n_in,
                              void* d_out, int out_size) {
    const float* kp_scores    = (const float*)d_in[0];
    const float* kp_desc      = (const float*)d_in[1];
    const float* scores_dense = (const float*)d_in[2];
    const float* desc_dense   = (const float*)d_in[3];
    float* out = (float*)d_out;

    cudaFuncSetAttribute(k_mma, cudaFuncAttributeMaxDynamicSharedMemorySize, GEMM_SMEM);
    cudaFuncSetAttribute(k_prep_dense, cudaFuncAttributeMaxDynamicSharedMemorySize, PREP_SMEM);

    k_prep_src<<<(B_ * N_ + 255) / 256, 256>>>(kp_desc);
    {
        dim3 gp(HW_ / 128, B_);
        k_prep_dense<<<gp, 256, PREP_SMEM>>>(desc_dense);
    }
    {
        dim3 gg(4, MT_, B_);
        k_mma<<<gg, 256, GEMM_SMEM>>>(out);
    }
    k_reduce<<<B_ * N_, 128>>>(out);
    k_scale<<<(size_t)B_ * N_ * HW_ / (4 * 256), 256>>>(out);
    k_tail<<<(B_ * N_) / 8, 256>>>(kp_scores, scores_dense, desc_dense, out);
}